// round 5
// baseline (speedup 1.0000x reference)
#include <cuda_runtime.h>

#define Nn 16
#define Cc 64
#define ICc 32
#define TVv 1600
#define EPSf 1e-5f

// ---------------- scratch (static device allocations) ----------------
__device__ float g_Q[Nn*TVv*ICc];     // query rows  (= k-projection of x)
__device__ float g_K[Nn*TVv*ICc];     // key rows    (= q-projection of x)
__device__ float g_V[Nn*TVv*ICc];     // value rows  (= v-projection of x)
__device__ float g_pt[Nn*Cc*TVv];     // Trans_s conv output, pre-BN, [N,C,TV]
__device__ float g_avgpart[Nn*13*64]; // per-block channel sums of x
__device__ float g_bnpart[400*128];   // per-CTA (sum, sumsq) per channel
__device__ float g_gate[Nn*Cc];
__device__ float g_bnscale[Cc];
__device__ float g_bnshift[Cc];

// ---------------- kernel 0: QKV projections + x channel sums ----------------
__global__ __launch_bounds__(128)
void proj_kernel(const float* __restrict__ x,
                 const float* __restrict__ Wv, const float* __restrict__ bv,
                 const float* __restrict__ Wk, const float* __restrict__ bk,
                 const float* __restrict__ Wq, const float* __restrict__ bq)
{
    __shared__ float sW[3*ICc*Cc];   // [Wk | Wq | Wv], each 32x64
    __shared__ float s_part[4*64];
    int tid = threadIdx.x;
    for (int i = tid; i < ICc*Cc; i += 128) {
        sW[i]            = Wk[i];
        sW[ICc*Cc + i]   = Wq[i];
        sW[2*ICc*Cc + i] = Wv[i];
    }
    int n = blockIdx.x / 13, chunk = blockIdx.x % 13;
    int tok = chunk*128 + tid;
    bool act = (tok < TVv);
    float xv[Cc];
    const float* xp = x + (long)n*Cc*TVv + tok;
    #pragma unroll
    for (int c = 0; c < Cc; c++) xv[c] = act ? xp[(long)c*TVv] : 0.f;

    // deterministic channel sums (avg-pool partials)
    int lane = tid & 31, warp = tid >> 5;
    #pragma unroll
    for (int c = 0; c < Cc; c++) {
        float v = xv[c];
        #pragma unroll
        for (int o = 16; o > 0; o >>= 1) v += __shfl_xor_sync(0xffffffffu, v, o);
        if (lane == 0) s_part[warp*64 + c] = v;
    }
    __syncthreads();
    if (tid < 64) {
        g_avgpart[blockIdx.x*64 + tid] =
            s_part[tid] + s_part[64+tid] + s_part[128+tid] + s_part[192+tid];
    }
    if (!act) return;

    long base = ((long)(n*TVv + tok)) * ICc;
    #pragma unroll
    for (int m = 0; m < 3; m++) {
        const float* W   = sW + m*ICc*Cc;
        const float* bp  = (m == 0) ? bk : ((m == 1) ? bq : bv);
        float* outb      = (m == 0) ? g_Q : ((m == 1) ? g_K : g_V);
        #pragma unroll
        for (int og = 0; og < ICc; og += 4) {
            float a0 = bp[og], a1 = bp[og+1], a2 = bp[og+2], a3 = bp[og+3];
            const float4* w0 = (const float4*)(W + (og  )*Cc);
            const float4* w1 = (const float4*)(W + (og+1)*Cc);
            const float4* w2 = (const float4*)(W + (og+2)*Cc);
            const float4* w3 = (const float4*)(W + (og+3)*Cc);
            #pragma unroll
            for (int i = 0; i < 16; i++) {
                float4 t;
                float v0 = xv[4*i], v1 = xv[4*i+1], v2 = xv[4*i+2], v3 = xv[4*i+3];
                t = w0[i]; a0 += t.x*v0 + t.y*v1 + t.z*v2 + t.w*v3;
                t = w1[i]; a1 += t.x*v0 + t.y*v1 + t.z*v2 + t.w*v3;
                t = w2[i]; a2 += t.x*v0 + t.y*v1 + t.z*v2 + t.w*v3;
                t = w3[i]; a3 += t.x*v0 + t.y*v1 + t.z*v2 + t.w*v3;
            }
            float4 st; st.x = a0; st.y = a1; st.z = a2; st.w = a3;
            *(float4*)(outb + base + og) = st;
        }
    }
}

// ---------------- kernel 1: flash attention + Trans conv + BN partials ----------------
// grid = 16*25 CTAs, block = 128 (64 queries x 2 key halves)
__global__ __launch_bounds__(128)
void attn_kernel(const float* __restrict__ Wt, const float* __restrict__ bt)
{
    __shared__ float sKV[4096];     // [Kh0|Kh1|Vh0|Vh1] (1024 each); later Wt (2048)
    __shared__ float sA[64*33];     // merge buffer, then padded p buffer
    __shared__ float s_bn[512];     // per-warp (sum,sq) x 64 channels

    int tid = threadIdx.x;
    int n  = blockIdx.x / 25, qt = blockIdx.x % 25;
    int q  = tid & 63, h = tid >> 6;
    int qtok = qt*64 + q;

    for (int i = tid; i < 512; i += 128) s_bn[i] = 0.f;

    float qv[ICc];
    const float4* Qp = (const float4*)(g_Q + ((long)(n*TVv + qtok)) * ICc);
    #pragma unroll
    for (int i = 0; i < 8; i++) {
        float4 t = Qp[i];
        qv[4*i] = t.x; qv[4*i+1] = t.y; qv[4*i+2] = t.z; qv[4*i+3] = t.w;
    }
    float acc[ICc];
    #pragma unroll
    for (int i = 0; i < ICc; i++) acc[i] = 0.f;
    float l = 0.f;

    const float4* Kb = (const float4*)(g_K + (long)n*TVv*ICc);
    const float4* Vb = (const float4*)(g_V + (long)n*TVv*ICc);

    for (int ch = 0; ch < 25; ch++) {
        __syncthreads();
        #pragma unroll
        for (int k = 0; k < 4; k++) {
            int j  = tid + k*128;        // 0..511 float4 slots
            int hh = j >> 8;
            int rr = (j >> 3) & 31;
            int ii = j & 7;
            int key = hh*800 + ch*32 + rr;
            ((float4*)sKV)[j]       = Kb[key*8 + ii];
            ((float4*)sKV)[512 + j] = Vb[key*8 + ii];
        }
        __syncthreads();
        const float* Ks = sKV + h*1024;
        const float* Vs = sKV + 2048 + h*1024;
        #pragma unroll 4
        for (int r = 0; r < 32; r++) {
            float d = 0.f;
            const float4* kr = (const float4*)(Ks + r*ICc);
            #pragma unroll
            for (int i = 0; i < 8; i++) {
                float4 t = kr[i];
                d += qv[4*i]*t.x + qv[4*i+1]*t.y + qv[4*i+2]*t.z + qv[4*i+3]*t.w;
            }
            float e = __expf(d);     // no-max softmax: |scores| are O(10) here, fp32-safe
            l += e;
            const float4* vr = (const float4*)(Vs + r*ICc);
            #pragma unroll
            for (int i = 0; i < 8; i++) {
                float4 t = vr[i];
                acc[4*i]   += e*t.x; acc[4*i+1] += e*t.y;
                acc[4*i+2] += e*t.z; acc[4*i+3] += e*t.w;
            }
        }
    }

    // merge key-split halves
    __syncthreads();
    if (h == 1) {
        sA[q*33 + 32] = l;
        #pragma unroll
        for (int i = 0; i < ICc; i++) sA[q*33 + i] = acc[i];
    }
    __syncthreads();
    if (h == 0) {
        float inv = 1.f / (l + sA[q*33 + 32]);
        #pragma unroll
        for (int i = 0; i < ICc; i++) sA[q*33 + i] = (acc[i] + sA[q*33 + i]) * inv;
    }
    __syncthreads();
    for (int i = tid; i < Cc*ICc; i += 128) sKV[i] = Wt[i];
    __syncthreads();

    // fused Trans_s 1x1 conv + BN partial sums
    int lane = tid & 31, warp = tid >> 5;
    long ptbase = (long)n*Cc*TVv + (long)qt*64;
    for (int k = 0; k < 32; k++) {
        int idx = tid + k*128;
        int c  = idx >> 6;      // uniform within a warp
        int qq = idx & 63;      // lane-contiguous
        float val = bt[c];
        const float* wr = sKV + c*ICc;
        const float* pr = sA + qq*33;
        #pragma unroll
        for (int i = 0; i < ICc; i++) val += wr[i] * pr[i];
        g_pt[ptbase + (long)c*TVv + qq] = val;

        float s = val, s2 = val*val;
        #pragma unroll
        for (int o = 16; o > 0; o >>= 1) {
            s  += __shfl_xor_sync(0xffffffffu, s,  o);
            s2 += __shfl_xor_sync(0xffffffffu, s2, o);
        }
        if (lane == 0) {
            s_bn[warp*128 + c]      += s;
            s_bn[warp*128 + 64 + c] += s2;
        }
    }
    __syncthreads();
    if (tid < 128) {
        g_bnpart[blockIdx.x*128 + tid] =
            s_bn[tid] + s_bn[128+tid] + s_bn[256+tid] + s_bn[384+tid];
    }
}

// ---------------- kernel 2: channel gate MLP + BN finalize ----------------
__global__ void gate_bn_kernel(const float* __restrict__ W1, const float* __restrict__ b1,
                               const float* __restrict__ W2, const float* __restrict__ b2,
                               const float* __restrict__ gamma, const float* __restrict__ beta)
{
    int t = threadIdx.x;   // 64 threads
    if (blockIdx.x < Nn) {
        int n = blockIdx.x;
        __shared__ float s_avg[64], s_h[4];
        float s = 0.f;
        for (int chnk = 0; chnk < 13; chnk++) s += g_avgpart[(n*13 + chnk)*64 + t];
        s_avg[t] = s * (1.f / (float)TVv);
        __syncthreads();
        if (t < 4) {
            float hsum = b1[t];
            for (int c = 0; c < 64; c++) hsum += W1[t*64 + c] * s_avg[c];
            s_h[t] = fmaxf(hsum, 0.f);
        }
        __syncthreads();
        float g = b2[t];
        #pragma unroll
        for (int j = 0; j < 4; j++) g += W2[t*4 + j] * s_h[j];
        g_gate[n*64 + t] = 1.f / (1.f + __expf(-g));
    } else {
        float s = 0.f, s2 = 0.f;
        for (int b = 0; b < 400; b++) {
            s  += g_bnpart[b*128 + t];
            s2 += g_bnpart[b*128 + 64 + t];
        }
        const float invN = 1.f / (float)(Nn * TVv);
        float mean = s * invN;
        float var  = s2 * invN - mean*mean;
        float sc   = gamma[t] * rsqrtf(var + EPSf);
        g_bnscale[t] = sc;
        g_bnshift[t] = beta[t] - mean*sc;
    }
}

// ---------------- kernel 3: gate * BN(pt) + x ----------------
__global__ void out_kernel(const float* __restrict__ x, float* __restrict__ out)
{
    int idx = blockIdx.x*256 + threadIdx.x;
    if (idx >= Nn*Cc*TVv) return;
    int c = (idx / TVv) & (Cc-1);
    int n = idx / (Cc*TVv);
    float g = g_gate[n*Cc + c];
    out[idx] = g * (g_pt[idx]*g_bnscale[c] + g_bnshift[c]) + x[idx];
}

// ---------------- launch ----------------
extern "C" void kernel_launch(void* const* d_in, const int* in_sizes, int n_in,
                              void* d_out, int out_size)
{
    const float* x     = (const float*)d_in[0];
    const float* Wv    = (const float*)d_in[1];
    const float* bv    = (const float*)d_in[2];
    const float* Wk    = (const float*)d_in[3];
    const float* bk    = (const float*)d_in[4];
    const float* Wq    = (const float*)d_in[5];
    const float* bq    = (const float*)d_in[6];
    const float* Wt    = (const float*)d_in[7];
    const float* bt    = (const float*)d_in[8];
    const float* gamma = (const float*)d_in[9];
    const float* beta  = (const float*)d_in[10];
    const float* W1    = (const float*)d_in[11];
    const float* b1    = (const float*)d_in[12];
    const float* W2    = (const float*)d_in[13];
    const float* b2    = (const float*)d_in[14];
    float* out = (float*)d_out;

    proj_kernel<<<Nn*13, 128>>>(x, Wv, bv, Wk, bk, Wq, bq);
    attn_kernel<<<Nn*25, 128>>>(Wt, bt);
    gate_bn_kernel<<<Nn+1, 64>>>(W1, b1, W2, b2, gamma, beta);
    out_kernel<<<(Nn*Cc*TVv + 255)/256, 256>>>(x, out);
}

// round 10
// speedup vs baseline: 1.1224x; 1.1224x over previous
#include <cuda_runtime.h>

#define Nn 16
#define Cc 64
#define ICc 32
#define TVv 1600
#define EPSf 1e-5f

typedef unsigned long long ull;

__device__ __forceinline__ ull pack2(float lo, float hi) {
    ull r; asm("mov.b64 %0, {%1, %2};" : "=l"(r) : "f"(lo), "f"(hi)); return r;
}
__device__ __forceinline__ void unpack2(ull v, float& lo, float& hi) {
    asm("mov.b64 {%0, %1}, %2;" : "=f"(lo), "=f"(hi) : "l"(v));
}
__device__ __forceinline__ ull ffma2(ull a, ull b, ull c) {
    ull d; asm("fma.rn.f32x2 %0, %1, %2, %3;" : "=l"(d) : "l"(a), "l"(b), "l"(c)); return d;
}

// ---------------- scratch (static device allocations) ----------------
__device__ float g_Q[Nn*TVv*ICc];
__device__ float g_K[Nn*TVv*ICc];
__device__ float g_V[Nn*TVv*ICc];
__device__ float g_pt[Nn*Cc*TVv];
__device__ float g_avgpart[Nn*13*64];
__device__ float g_bnpart[400*128];
__device__ float g_gate[Nn*Cc];
__device__ float g_bnscale[Cc];
__device__ float g_bnshift[Cc];

// ---------------- kernel 0: QKV projections + x channel sums ----------------
__global__ __launch_bounds__(128)
void proj_kernel(const float* __restrict__ x,
                 const float* __restrict__ Wv, const float* __restrict__ bv,
                 const float* __restrict__ Wk, const float* __restrict__ bk,
                 const float* __restrict__ Wq, const float* __restrict__ bq)
{
    __shared__ float sW[3*ICc*Cc];
    __shared__ float s_part[4*64];
    int tid = threadIdx.x;
    for (int i = tid; i < ICc*Cc; i += 128) {
        sW[i]            = Wk[i];
        sW[ICc*Cc + i]   = Wq[i];
        sW[2*ICc*Cc + i] = Wv[i];
    }
    int n = blockIdx.x / 13, chunk = blockIdx.x % 13;
    int tok = chunk*128 + tid;
    bool act = (tok < TVv);
    const float* xp = x + (long)n*Cc*TVv + tok;

    int lane = tid & 31, warp = tid >> 5;
    ull xp2[32];
    #pragma unroll
    for (int cp = 0; cp < 32; cp++) {
        float v0 = act ? xp[(long)(2*cp)  *TVv] : 0.f;
        float v1 = act ? xp[(long)(2*cp+1)*TVv] : 0.f;
        xp2[cp] = pack2(v0, v1);
        float s0 = v0, s1 = v1;
        #pragma unroll
        for (int o = 16; o > 0; o >>= 1) {
            s0 += __shfl_xor_sync(0xffffffffu, s0, o);
            s1 += __shfl_xor_sync(0xffffffffu, s1, o);
        }
        if (lane == 0) {
            s_part[warp*64 + 2*cp]   = s0;
            s_part[warp*64 + 2*cp+1] = s1;
        }
    }
    __syncthreads();
    if (tid < 64) {
        g_avgpart[blockIdx.x*64 + tid] =
            s_part[tid] + s_part[64+tid] + s_part[128+tid] + s_part[192+tid];
    }
    if (!act) return;

    long base = ((long)(n*TVv + tok)) * ICc;
    for (int m = 0; m < 3; m++) {
        const float* W  = sW + m*ICc*Cc;
        const float* bp = (m == 0) ? bk : ((m == 1) ? bq : bv);
        float* outb     = (m == 0) ? g_Q : ((m == 1) ? g_K : g_V);
        #pragma unroll
        for (int og = 0; og < ICc; og += 4) {
            ull A[8];
            #pragma unroll
            for (int j = 0; j < 8; j++) A[j] = 0ULL;
            const ulonglong2* w0 = (const ulonglong2*)(W + (og  )*Cc);
            const ulonglong2* w1 = (const ulonglong2*)(W + (og+1)*Cc);
            const ulonglong2* w2 = (const ulonglong2*)(W + (og+2)*Cc);
            const ulonglong2* w3 = (const ulonglong2*)(W + (og+3)*Cc);
            #pragma unroll
            for (int i = 0; i < 16; i++) {
                ulonglong2 t0 = w0[i], t1 = w1[i], t2 = w2[i], t3 = w3[i];
                A[0] = ffma2(xp2[2*i], t0.x, A[0]); A[1] = ffma2(xp2[2*i+1], t0.y, A[1]);
                A[2] = ffma2(xp2[2*i], t1.x, A[2]); A[3] = ffma2(xp2[2*i+1], t1.y, A[3]);
                A[4] = ffma2(xp2[2*i], t2.x, A[4]); A[5] = ffma2(xp2[2*i+1], t2.y, A[5]);
                A[6] = ffma2(xp2[2*i], t3.x, A[6]); A[7] = ffma2(xp2[2*i+1], t3.y, A[7]);
            }
            float4 st;
            {
                float a0,a1,b0,b1;
                unpack2(A[0],a0,a1); unpack2(A[1],b0,b1); st.x = bp[og  ] + ((a0+b0)+(a1+b1));
                unpack2(A[2],a0,a1); unpack2(A[3],b0,b1); st.y = bp[og+1] + ((a0+b0)+(a1+b1));
                unpack2(A[4],a0,a1); unpack2(A[5],b0,b1); st.z = bp[og+2] + ((a0+b0)+(a1+b1));
                unpack2(A[6],a0,a1); unpack2(A[7],b0,b1); st.w = bp[og+3] + ((a0+b0)+(a1+b1));
            }
            *(float4*)(outb + base + og) = st;
        }
    }
}

// ---------------- kernel 1: flash attention + Trans conv + BN partials ----------------
// grid = 16*25 CTAs, block = 128 (64 queries x 2 key halves)
__global__ __launch_bounds__(128)
void attn_kernel(const float* __restrict__ Wt, const float* __restrict__ bt)
{
    __shared__ float sKV[4096];     // [Kh0|Kh1|Vh0|Vh1] (1024 each); later Wt (2048)
    __shared__ float sA[64*36];     // merge buffer / padded p buffer (16B-aligned rows)
    __shared__ float s_bn[512];

    int tid = threadIdx.x;
    int n  = blockIdx.x / 25, qt = blockIdx.x % 25;
    int q  = tid & 63, h = tid >> 6;
    int qtok = qt*64 + q;

    for (int i = tid; i < 512; i += 128) s_bn[i] = 0.f;

    ull qp2[16];
    const float4* Qp = (const float4*)(g_Q + ((long)(n*TVv + qtok)) * ICc);
    #pragma unroll
    for (int i = 0; i < 8; i++) {
        float4 t = Qp[i];
        qp2[2*i]   = pack2(t.x, t.y);
        qp2[2*i+1] = pack2(t.z, t.w);
    }
    ull acc2[16];
    #pragma unroll
    for (int i = 0; i < 16; i++) acc2[i] = 0ULL;
    float l = 0.f;

    const float4* Kb = (const float4*)(g_K + (long)n*TVv*ICc);
    const float4* Vb = (const float4*)(g_V + (long)n*TVv*ICc);

    for (int ch = 0; ch < 25; ch++) {
        __syncthreads();
        #pragma unroll
        for (int k = 0; k < 4; k++) {
            int j  = tid + k*128;
            int hh = j >> 8;
            int rr = (j >> 3) & 31;
            int ii = j & 7;
            int key = hh*800 + ch*32 + rr;
            ((float4*)sKV)[j]       = Kb[key*8 + ii];
            ((float4*)sKV)[512 + j] = Vb[key*8 + ii];
        }
        __syncthreads();
        const float* Ks = sKV + h*1024;
        const float* Vs = sKV + 2048 + h*1024;
        #pragma unroll 4
        for (int r = 0; r < 32; r++) {
            const ulonglong2* kr = (const ulonglong2*)(Ks + r*ICc);
            ull da = 0ULL, db = 0ULL;
            #pragma unroll
            for (int i = 0; i < 8; i++) {
                ulonglong2 t = kr[i];
                da = ffma2(qp2[2*i],   t.x, da);
                db = ffma2(qp2[2*i+1], t.y, db);
            }
            float a0, a1, b0, b1;
            unpack2(da, a0, a1); unpack2(db, b0, b1);
            float e = __expf((a0 + b0) + (a1 + b1));
            l += e;
            ull ee = pack2(e, e);
            const ulonglong2* vr = (const ulonglong2*)(Vs + r*ICc);
            #pragma unroll
            for (int i = 0; i < 8; i++) {
                ulonglong2 t = vr[i];
                acc2[2*i]   = ffma2(ee, t.x, acc2[2*i]);
                acc2[2*i+1] = ffma2(ee, t.y, acc2[2*i+1]);
            }
        }
    }

    // merge key-split halves
    __syncthreads();
    if (h == 1) {
        sA[q*36 + 32] = l;
        #pragma unroll
        for (int i = 0; i < 16; i++) {
            float lo, hi; unpack2(acc2[i], lo, hi);
            sA[q*36 + 2*i]   = lo;
            sA[q*36 + 2*i+1] = hi;
        }
    }
    __syncthreads();
    if (h == 0) {
        float inv = 1.f / (l + sA[q*36 + 32]);
        #pragma unroll
        for (int i = 0; i < 16; i++) {
            float lo, hi; unpack2(acc2[i], lo, hi);
            sA[q*36 + 2*i]   = (lo + sA[q*36 + 2*i])   * inv;
            sA[q*36 + 2*i+1] = (hi + sA[q*36 + 2*i+1]) * inv;
        }
    }
    __syncthreads();
    for (int i = tid; i < Cc*ICc; i += 128) sKV[i] = Wt[i];
    __syncthreads();

    // fused Trans_s 1x1 conv + BN partial sums
    int lane = tid & 31, warp = tid >> 5;
    long ptbase = (long)n*Cc*TVv + (long)qt*64;
    for (int k = 0; k < 32; k++) {
        int idx = tid + k*128;
        int c  = idx >> 6;
        int qq = idx & 63;
        const ulonglong2* wr = (const ulonglong2*)(sKV + c*ICc);
        const ulonglong2* pr = (const ulonglong2*)(sA + qq*36);
        ull va = 0ULL, vb = 0ULL;
        #pragma unroll
        for (int i = 0; i < 8; i++) {
            ulonglong2 w = wr[i], p = pr[i];
            va = ffma2(w.x, p.x, va);
            vb = ffma2(w.y, p.y, vb);
        }
        float a0, a1, b0, b1;
        unpack2(va, a0, a1); unpack2(vb, b0, b1);
        float val = bt[c] + ((a0 + b0) + (a1 + b1));
        g_pt[ptbase + (long)c*TVv + qq] = val;

        float s = val, s2 = val*val;
        #pragma unroll
        for (int o = 16; o > 0; o >>= 1) {
            s  += __shfl_xor_sync(0xffffffffu, s,  o);
            s2 += __shfl_xor_sync(0xffffffffu, s2, o);
        }
        if (lane == 0) {
            s_bn[warp*128 + c]      += s;
            s_bn[warp*128 + 64 + c] += s2;
        }
    }
    __syncthreads();
    if (tid < 128) {
        g_bnpart[blockIdx.x*128 + tid] =
            s_bn[tid] + s_bn[128+tid] + s_bn[256+tid] + s_bn[384+tid];
    }
}

// ---------------- kernel 2: channel gate MLP + BN finalize ----------------
__global__ __launch_bounds__(256)
void gate_bn_kernel(const float* __restrict__ W1, const float* __restrict__ b1,
                    const float* __restrict__ W2, const float* __restrict__ b2,
                    const float* __restrict__ gamma, const float* __restrict__ beta)
{
    int t = threadIdx.x;
    if (blockIdx.x < Nn) {
        int n = blockIdx.x;
        __shared__ float s_avg[64], s_h[4];
        if (t < 64) {
            float s = 0.f;
            for (int chnk = 0; chnk < 13; chnk++) s += g_avgpart[(n*13 + chnk)*64 + t];
            s_avg[t] = s * (1.f / (float)TVv);
        }
        __syncthreads();
        if (t < 4) {
            float hsum = b1[t];
            for (int c = 0; c < 64; c++) hsum += W1[t*64 + c] * s_avg[c];
            s_h[t] = fmaxf(hsum, 0.f);
        }
        __syncthreads();
        if (t < 64) {
            float g = b2[t];
            #pragma unroll
            for (int j = 0; j < 4; j++) g += W2[t*4 + j] * s_h[j];
            g_gate[n*64 + t] = 1.f / (1.f + __expf(-g));
        }
    } else {
        __shared__ float rs[4][64], rs2[4][64];
        int ch = t & 63, pp = t >> 6;
        float s = 0.f, s2 = 0.f;
        for (int b = pp*100; b < pp*100 + 100; b++) {
            s  += g_bnpart[b*128 + ch];
            s2 += g_bnpart[b*128 + 64 + ch];
        }
        rs[pp][ch] = s; rs2[pp][ch] = s2;
        __syncthreads();
        if (t < 64) {
            float ts  = (rs[0][t]  + rs[1][t])  + (rs[2][t]  + rs[3][t]);
            float ts2 = (rs2[0][t] + rs2[1][t]) + (rs2[2][t] + rs2[3][t]);
            const float invN = 1.f / (float)(Nn * TVv);
            float mean = ts * invN;
            float var  = ts2 * invN - mean*mean;
            float sc   = gamma[t] * rsqrtf(var + EPSf);
            g_bnscale[t] = sc;
            g_bnshift[t] = beta[t] - mean*sc;
        }
    }
}

// ---------------- kernel 3: gate * BN(pt) + x  (float4 vectorized) ----------------
__global__ void out_kernel(const float4* __restrict__ x4, float4* __restrict__ out4)
{
    int i = blockIdx.x*256 + threadIdx.x;
    if (i >= Nn*Cc*(TVv/4)) return;
    int c = (i / (TVv/4)) & (Cc-1);
    int n = i / ((TVv/4)*Cc);
    float g  = g_gate[n*Cc + c];
    float sc = g_bnscale[c], sh = g_bnshift[c];
    float4 p  = ((const float4*)g_pt)[i];
    float4 xv = x4[i];
    float4 o;
    o.x = g*(p.x*sc + sh) + xv.x;
    o.y = g*(p.y*sc + sh) + xv.y;
    o.z = g*(p.z*sc + sh) + xv.z;
    o.w = g*(p.w*sc + sh) + xv.w;
    out4[i] = o;
}

// ---------------- launch ----------------
extern "C" void kernel_launch(void* const* d_in, const int* in_sizes, int n_in,
                              void* d_out, int out_size)
{
    const float* x     = (const float*)d_in[0];
    const float* Wv    = (const float*)d_in[1];
    const float* bv    = (const float*)d_in[2];
    const float* Wk    = (const float*)d_in[3];
    const float* bk    = (const float*)d_in[4];
    const float* Wq    = (const float*)d_in[5];
    const float* bq    = (const float*)d_in[6];
    const float* Wt    = (const float*)d_in[7];
    const float* bt    = (const float*)d_in[8];
    const float* gamma = (const float*)d_in[9];
    const float* beta  = (const float*)d_in[10];
    const float* W1    = (const float*)d_in[11];
    const float* b1    = (const float*)d_in[12];
    const float* W2    = (const float*)d_in[13];
    const float* b2    = (const float*)d_in[14];
    float* out = (float*)d_out;

    proj_kernel<<<Nn*13, 128>>>(x, Wv, bv, Wk, bk, Wq, bq);
    attn_kernel<<<Nn*25, 128>>>(Wt, bt);
    gate_bn_kernel<<<Nn+1, 256>>>(W1, b1, W2, b2, gamma, beta);
    out_kernel<<<(Nn*Cc*(TVv/4) + 255)/256, 256>>>((const float4*)x, (float4*)d_out);
}

// round 14
// speedup vs baseline: 2.2584x; 2.0121x over previous
#include <cuda_runtime.h>
#include <cuda_bf16.h>

#define Nn 16
#define Cc 64
#define ICc 32
#define TVv 1600
#define QT 25              // query tiles of 64 per batch
#define NCTA (Nn*QT)       // 400
#define EPSf 1e-5f

typedef unsigned long long ull;
typedef unsigned int u32;

__device__ __forceinline__ ull pack2(float lo, float hi) {
    ull r; asm("mov.b64 %0, {%1, %2};" : "=l"(r) : "f"(lo), "f"(hi)); return r;
}
__device__ __forceinline__ void unpack2(ull v, float& lo, float& hi) {
    asm("mov.b64 {%0, %1}, %2;" : "=f"(lo), "=f"(hi) : "l"(v));
}
__device__ __forceinline__ ull ffma2(ull a, ull b, ull c) {
    ull d; asm("fma.rn.f32x2 %0, %1, %2, %3;" : "=l"(d) : "l"(a), "l"(b), "l"(c)); return d;
}

// m16n8k16 row.col bf16 -> f32, D accumulates in place
__device__ __forceinline__ void mma16816(float* c, const u32* a, u32 b0, u32 b1) {
    asm volatile(
        "mma.sync.aligned.m16n8k16.row.col.f32.bf16.bf16.f32 "
        "{%0,%1,%2,%3}, {%4,%5,%6,%7}, {%8,%9}, {%0,%1,%2,%3};"
        : "+f"(c[0]), "+f"(c[1]), "+f"(c[2]), "+f"(c[3])
        : "r"(a[0]), "r"(a[1]), "r"(a[2]), "r"(a[3]), "r"(b0), "r"(b1));
}

// pack two floats into bf16x2 hi + bf16x2 lo (hi/lo split)
__device__ __forceinline__ void split2(float a, float b, u32& hi, u32& lo) {
    __nv_bfloat16 ha = __float2bfloat16(a), hb = __float2bfloat16(b);
    __nv_bfloat162 H; H.x = ha; H.y = hb;
    __nv_bfloat162 L;
    L.x = __float2bfloat16(a - __bfloat162float(ha));
    L.y = __float2bfloat16(b - __bfloat162float(hb));
    hi = *(u32*)&H; lo = *(u32*)&L;
}

// ---------------- scratch ----------------
__device__ __nv_bfloat16 g_Qh[Nn*TVv*ICc];   // flash-queries (k_x), token-major
__device__ __nv_bfloat16 g_Ql[Nn*TVv*ICc];
__device__ __nv_bfloat16 g_Kh[Nn*TVv*ICc];   // flash-keys (q_x), token-major
__device__ __nv_bfloat16 g_Kl[Nn*TVv*ICc];
__device__ __nv_bfloat16 g_Vth[Nn*ICc*TVv];  // values channel-major [n][ic][tv]
__device__ __nv_bfloat16 g_Vtl[Nn*ICc*TVv];
__device__ float g_pt[Nn*Cc*TVv];
__device__ float g_avgpart[Nn*13*64];
__device__ float g_bnpart[NCTA*128];
__device__ float g_gate[Nn*Cc];
__device__ float g_bnscale[Cc];
__device__ float g_bnshift[Cc];

// ---------------- kernel 0: QKV projections (bf16 hi/lo) + x channel sums ----------------
__global__ __launch_bounds__(128)
void proj_kernel(const float* __restrict__ x,
                 const float* __restrict__ Wv, const float* __restrict__ bv,
                 const float* __restrict__ Wk, const float* __restrict__ bk,
                 const float* __restrict__ Wq, const float* __restrict__ bq)
{
    __shared__ float sW[3*ICc*Cc];
    __shared__ float s_part[4*64];
    int tid = threadIdx.x;
    for (int i = tid; i < ICc*Cc; i += 128) {
        sW[i]            = Wk[i];   // flash-Q from Wk (k_x rows of A)
        sW[ICc*Cc + i]   = Wq[i];   // flash-K from Wq (q_x cols of A)
        sW[2*ICc*Cc + i] = Wv[i];
    }
    int n = blockIdx.x / 13, chunk = blockIdx.x % 13;
    int tok = chunk*128 + tid;
    bool act = (tok < TVv);
    const float* xp = x + (long)n*Cc*TVv + tok;

    int lane = tid & 31, warp = tid >> 5;
    ull xp2[32];
    #pragma unroll
    for (int cp = 0; cp < 32; cp++) {
        float v0 = act ? xp[(long)(2*cp)  *TVv] : 0.f;
        float v1 = act ? xp[(long)(2*cp+1)*TVv] : 0.f;
        xp2[cp] = pack2(v0, v1);
        float s0 = v0, s1 = v1;
        #pragma unroll
        for (int o = 16; o > 0; o >>= 1) {
            s0 += __shfl_xor_sync(0xffffffffu, s0, o);
            s1 += __shfl_xor_sync(0xffffffffu, s1, o);
        }
        if (lane == 0) { s_part[warp*64 + 2*cp] = s0; s_part[warp*64 + 2*cp+1] = s1; }
    }
    __syncthreads();
    if (tid < 64) {
        g_avgpart[blockIdx.x*64 + tid] =
            s_part[tid] + s_part[64+tid] + s_part[128+tid] + s_part[192+tid];
    }
    if (!act) return;

    for (int m = 0; m < 3; m++) {
        const float* W  = sW + m*ICc*Cc;
        const float* bp = (m == 0) ? bk : ((m == 1) ? bq : bv);
        u32 rowHi[16], rowLo[16];
        #pragma unroll
        for (int og = 0; og < ICc; og += 4) {
            ull A[8];
            #pragma unroll
            for (int j = 0; j < 8; j++) A[j] = 0ULL;
            const ulonglong2* w0 = (const ulonglong2*)(W + (og  )*Cc);
            const ulonglong2* w1 = (const ulonglong2*)(W + (og+1)*Cc);
            const ulonglong2* w2 = (const ulonglong2*)(W + (og+2)*Cc);
            const ulonglong2* w3 = (const ulonglong2*)(W + (og+3)*Cc);
            #pragma unroll
            for (int i = 0; i < 16; i++) {
                ulonglong2 t0 = w0[i], t1 = w1[i], t2 = w2[i], t3 = w3[i];
                A[0] = ffma2(xp2[2*i], t0.x, A[0]); A[1] = ffma2(xp2[2*i+1], t0.y, A[1]);
                A[2] = ffma2(xp2[2*i], t1.x, A[2]); A[3] = ffma2(xp2[2*i+1], t1.y, A[3]);
                A[4] = ffma2(xp2[2*i], t2.x, A[4]); A[5] = ffma2(xp2[2*i+1], t2.y, A[5]);
                A[6] = ffma2(xp2[2*i], t3.x, A[6]); A[7] = ffma2(xp2[2*i+1], t3.y, A[7]);
            }
            float4 st;
            {
                float a0,a1,b0,b1;
                unpack2(A[0],a0,a1); unpack2(A[1],b0,b1); st.x = bp[og  ] + ((a0+b0)+(a1+b1));
                unpack2(A[2],a0,a1); unpack2(A[3],b0,b1); st.y = bp[og+1] + ((a0+b0)+(a1+b1));
                unpack2(A[4],a0,a1); unpack2(A[5],b0,b1); st.z = bp[og+2] + ((a0+b0)+(a1+b1));
                unpack2(A[6],a0,a1); unpack2(A[7],b0,b1); st.w = bp[og+3] + ((a0+b0)+(a1+b1));
            }
            if (m < 2) {
                split2(st.x, st.y, rowHi[og/2],   rowLo[og/2]);
                split2(st.z, st.w, rowHi[og/2+1], rowLo[og/2+1]);
            } else {
                long vb = (long)n*ICc*TVv + tok;
                float vv[4] = {st.x, st.y, st.z, st.w};
                #pragma unroll
                for (int j = 0; j < 4; j++) {
                    __nv_bfloat16 h = __float2bfloat16(vv[j]);
                    g_Vth[vb + (long)(og+j)*TVv] = h;
                    g_Vtl[vb + (long)(og+j)*TVv] = __float2bfloat16(vv[j] - __bfloat162float(h));
                }
            }
        }
        if (m == 0) {
            uint4* qh = (uint4*)(g_Qh + ((long)(n*TVv + tok))*ICc);
            uint4* ql = (uint4*)(g_Ql + ((long)(n*TVv + tok))*ICc);
            #pragma unroll
            for (int i = 0; i < 4; i++) {
                qh[i] = make_uint4(rowHi[4*i], rowHi[4*i+1], rowHi[4*i+2], rowHi[4*i+3]);
                ql[i] = make_uint4(rowLo[4*i], rowLo[4*i+1], rowLo[4*i+2], rowLo[4*i+3]);
            }
        } else if (m == 1) {
            uint4* kh = (uint4*)(g_Kh + ((long)(n*TVv + tok))*ICc);
            uint4* kl = (uint4*)(g_Kl + ((long)(n*TVv + tok))*ICc);
            #pragma unroll
            for (int i = 0; i < 4; i++) {
                kh[i] = make_uint4(rowHi[4*i], rowHi[4*i+1], rowHi[4*i+2], rowHi[4*i+3]);
                kl[i] = make_uint4(rowLo[4*i], rowLo[4*i+1], rowLo[4*i+2], rowLo[4*i+3]);
            }
        }
    }
}

// ---------------- kernel 1: HMMA flash attention + Trans conv + BN partials ----------------
// smem layout (bytes). K tile: [64 keys][40 feats pad] bf16 = 5120B per split.
//                      V tile: [32 ic][72 toks pad] bf16 = 4608B per split.
#define KROW 80     // bytes per K smem row (40 bf16)
#define VROW 144    // bytes per V smem row (72 bf16)
#define OFF_KH0  0
#define OFF_KL0  5120
#define OFF_KH1  10240
#define OFF_KL1  15360
#define OFF_VH0  20480
#define OFF_VL0  25088
#define OFF_VH1  29696
#define OFF_VL1  34304
#define OFF_WT   38912
#define OFF_SA   47104        // 64 rows x 36 floats (144B rows)
#define DSM_BYTES (47104 + 9216)

__global__ __launch_bounds__(128)
void attn_kernel(const float* __restrict__ Wt, const float* __restrict__ bt)
{
    extern __shared__ char B[];
    __shared__ float s_bn[4*128];

    int tid = threadIdx.x, lane = tid & 31, warp = tid >> 5;
    int n = blockIdx.x / QT, qt = blockIdx.x % QT;
    int r  = lane >> 2;          // row within 16-row fragment
    int t2 = (lane & 3) * 2;     // col pair base

    for (int i = tid; i < 512; i += 128) s_bn[i] = 0.f;

    // stage Wt
    for (int i = tid; i < Cc*ICc; i += 128) ((float*)(B + OFF_WT))[i] = Wt[i];

    // ---- load Q fragments (per-warp 16 queries), hi and lo ----
    int qbase = qt*64 + warp*16;
    u32 aQh[8], aQl[8];
    {
        long i0 = ((long)(n*TVv + qbase + r))*ICc;
        #pragma unroll
        for (int kc = 0; kc < 2; kc++) {
            int f = kc*16 + t2;
            aQh[kc*4+0] = *(const u32*)(g_Qh + i0 + f);
            aQh[kc*4+1] = *(const u32*)(g_Qh + i0 + 8*ICc + f);
            aQh[kc*4+2] = *(const u32*)(g_Qh + i0 + f + 8);
            aQh[kc*4+3] = *(const u32*)(g_Qh + i0 + 8*ICc + f + 8);
            aQl[kc*4+0] = *(const u32*)(g_Ql + i0 + f);
            aQl[kc*4+1] = *(const u32*)(g_Ql + i0 + 8*ICc + f);
            aQl[kc*4+2] = *(const u32*)(g_Ql + i0 + f + 8);
            aQl[kc*4+3] = *(const u32*)(g_Ql + i0 + 8*ICc + f + 8);
        }
    }

    float O[16];
    #pragma unroll
    for (int i = 0; i < 16; i++) O[i] = 0.f;
    float l0 = 0.f, l1 = 0.f;

    // ---- copy helper for chunk staging ----
    // K: 256 uint4 per split; V: 256 uint4 per split.
    auto stage = [&](int c, int buf) {
        const uint4* kh = (const uint4*)(g_Kh + ((long)(n*TVv + c*64))*ICc);
        const uint4* kl = (const uint4*)(g_Kl + ((long)(n*TVv + c*64))*ICc);
        char* KH = B + (buf ? OFF_KH1 : OFF_KH0);
        char* KL = B + (buf ? OFF_KL1 : OFF_KL0);
        #pragma unroll
        for (int t = 0; t < 2; t++) {
            int i = tid + t*128;          // 0..255
            int row = i >> 2, seg = i & 3;
            *(uint4*)(KH + row*KROW + seg*16) = kh[i];
            *(uint4*)(KL + row*KROW + seg*16) = kl[i];
        }
        char* VH = B + (buf ? OFF_VH1 : OFF_VH0);
        char* VL = B + (buf ? OFF_VL1 : OFF_VL0);
        #pragma unroll
        for (int t = 0; t < 2; t++) {
            int i = tid + t*128;
            int row = i >> 3, seg = i & 7;
            const uint4* vh = (const uint4*)(g_Vth + ((long)(n*ICc + row))*TVv + c*64);
            const uint4* vl = (const uint4*)(g_Vtl + ((long)(n*ICc + row))*TVv + c*64);
            *(uint4*)(VH + row*VROW + seg*16) = vh[seg];
            *(uint4*)(VL + row*VROW + seg*16) = vl[seg];
        }
    };

    stage(0, 0);
    __syncthreads();

    for (int c = 0; c < 25; c++) {
        int buf = c & 1;
        if (c < 24) stage(c+1, 1-buf);

        const char* KH = B + (buf ? OFF_KH1 : OFF_KH0);
        const char* KL = B + (buf ? OFF_KL1 : OFF_KL0);
        const char* VH = B + (buf ? OFF_VH1 : OFF_VH0);
        const char* VL = B + (buf ? OFF_VL1 : OFF_VL0);

        #pragma unroll
        for (int m = 0; m < 4; m++) {
            // ---- S tiles for keys m*16 .. m*16+15 (two 8-key subtiles) ----
            float e[8];
            #pragma unroll
            for (int sub = 0; sub < 2; sub++) {
                float c4[4] = {0.f, 0.f, 0.f, 0.f};
                int keyb = m*16 + sub*8;
                const char* krh = KH + (keyb + r)*KROW + t2*2;
                const char* krl = KL + (keyb + r)*KROW + t2*2;
                #pragma unroll
                for (int kc = 0; kc < 2; kc++) {
                    u32 bh0 = *(const u32*)(krh + kc*32);
                    u32 bh1 = *(const u32*)(krh + kc*32 + 16);
                    mma16816(c4, aQh + kc*4, bh0, bh1);
                    mma16816(c4, aQl + kc*4, bh0, bh1);
                    u32 bl0 = *(const u32*)(krl + kc*32);
                    u32 bl1 = *(const u32*)(krl + kc*32 + 16);
                    mma16816(c4, aQh + kc*4, bl0, bl1);
                }
                float e0 = __expf(c4[0]), e1 = __expf(c4[1]);
                float e2 = __expf(c4[2]), e3 = __expf(c4[3]);
                l0 += e0 + e1; l1 += e2 + e3;
                e[sub*4+0] = e0; e[sub*4+1] = e1; e[sub*4+2] = e2; e[sub*4+3] = e3;
            }
            // ---- build P fragments (A-operand layout == C layout) ----
            u32 aPh[4], aPl[4];
            split2(e[0], e[1], aPh[0], aPl[0]);   // rows r,   keys sub0
            split2(e[2], e[3], aPh[1], aPl[1]);   // rows r+8, keys sub0
            split2(e[4], e[5], aPh[2], aPl[2]);   // rows r,   keys sub1
            split2(e[6], e[7], aPh[3], aPl[3]);   // rows r+8, keys sub1
            // ---- O += P * V for this 16-key slab ----
            #pragma unroll
            for (int jo = 0; jo < 4; jo++) {
                const char* vrh = VH + (jo*8 + r)*VROW + (m*16 + t2)*2;
                const char* vrl = VL + (jo*8 + r)*VROW + (m*16 + t2)*2;
                u32 bh0 = *(const u32*)(vrh);
                u32 bh1 = *(const u32*)(vrh + 16);
                mma16816(O + jo*4, aPh, bh0, bh1);
                mma16816(O + jo*4, aPl, bh0, bh1);
                u32 bl0 = *(const u32*)(vrl);
                u32 bl1 = *(const u32*)(vrl + 16);
                mma16816(O + jo*4, aPh, bl0, bl1);
            }
        }
        __syncthreads();
    }

    // ---- reduce l across the 4 lanes of each row group ----
    #pragma unroll
    for (int o = 1; o <= 2; o <<= 1) {
        l0 += __shfl_xor_sync(0xffffffffu, l0, o);
        l1 += __shfl_xor_sync(0xffffffffu, l1, o);
    }
    float inv0 = 1.f / l0, inv1 = 1.f / l1;

    // ---- write normalized p to sA [64 q][36 floats] ----
    float* SA = (float*)(B + OFF_SA);
    #pragma unroll
    for (int jo = 0; jo < 4; jo++) {
        int q0 = warp*16 + r;
        float2 v0; v0.x = O[jo*4+0]*inv0; v0.y = O[jo*4+1]*inv0;
        float2 v1; v1.x = O[jo*4+2]*inv1; v1.y = O[jo*4+3]*inv1;
        *(float2*)(SA + q0*36 + jo*8 + t2)       = v0;
        *(float2*)(SA + (q0+8)*36 + jo*8 + t2)   = v1;
    }
    __syncthreads();

    // ---- fused Trans_s 1x1 conv + BN partial sums (64 q x 64 ch) ----
    long ptbase = (long)n*Cc*TVv + (long)qt*64;
    const ulonglong2* Wts = (const ulonglong2*)(B + OFF_WT);
    for (int k = 0; k < 32; k++) {
        int idx = tid + k*128;
        int c2 = idx >> 6;
        int qq = idx & 63;
        const ulonglong2* wr = Wts + c2*8;
        const ulonglong2* pr = (const ulonglong2*)(SA + qq*36);
        ull va = 0ULL, vb = 0ULL;
        #pragma unroll
        for (int i = 0; i < 8; i++) {
            ulonglong2 w = wr[i], p = pr[i];
            va = ffma2(w.x, p.x, va);
            vb = ffma2(w.y, p.y, vb);
        }
        float a0, a1, b0, b1;
        unpack2(va, a0, a1); unpack2(vb, b0, b1);
        float val = bt[c2] + ((a0 + b0) + (a1 + b1));
        g_pt[ptbase + (long)c2*TVv + qq] = val;

        float s = val, s2 = val*val;
        #pragma unroll
        for (int o = 16; o > 0; o >>= 1) {
            s  += __shfl_xor_sync(0xffffffffu, s,  o);
            s2 += __shfl_xor_sync(0xffffffffu, s2, o);
        }
        if (lane == 0) {
            s_bn[warp*128 + c2]      += s;
            s_bn[warp*128 + 64 + c2] += s2;
        }
    }
    __syncthreads();
    if (tid < 128) {
        g_bnpart[blockIdx.x*128 + tid] =
            s_bn[tid] + s_bn[128+tid] + s_bn[256+tid] + s_bn[384+tid];
    }
}

// ---------------- kernel 2: channel gate MLP + BN finalize ----------------
__global__ __launch_bounds__(256)
void gate_bn_kernel(const float* __restrict__ W1, const float* __restrict__ b1,
                    const float* __restrict__ W2, const float* __restrict__ b2,
                    const float* __restrict__ gamma, const float* __restrict__ beta)
{
    int t = threadIdx.x;
    if (blockIdx.x < Nn) {
        int n = blockIdx.x;
        __shared__ float s_avg[64], s_h[4];
        if (t < 64) {
            float s = 0.f;
            for (int chnk = 0; chnk < 13; chnk++) s += g_avgpart[(n*13 + chnk)*64 + t];
            s_avg[t] = s * (1.f / (float)TVv);
        }
        __syncthreads();
        if (t < 4) {
            float hsum = b1[t];
            for (int c = 0; c < 64; c++) hsum += W1[t*64 + c] * s_avg[c];
            s_h[t] = fmaxf(hsum, 0.f);
        }
        __syncthreads();
        if (t < 64) {
            float g = b2[t];
            #pragma unroll
            for (int j = 0; j < 4; j++) g += W2[t*4 + j] * s_h[j];
            g_gate[n*64 + t] = 1.f / (1.f + __expf(-g));
        }
    } else {
        __shared__ float rs[4][64], rs2[4][64];
        int ch = t & 63, pp = t >> 6;
        float s = 0.f, s2 = 0.f;
        for (int b = pp*100; b < pp*100 + 100; b++) {
            s  += g_bnpart[b*128 + ch];
            s2 += g_bnpart[b*128 + 64 + ch];
        }
        rs[pp][ch] = s; rs2[pp][ch] = s2;
        __syncthreads();
        if (t < 64) {
            float ts  = (rs[0][t]  + rs[1][t])  + (rs[2][t]  + rs[3][t]);
            float ts2 = (rs2[0][t] + rs2[1][t]) + (rs2[2][t] + rs2[3][t]);
            const float invN = 1.f / (float)(Nn * TVv);
            float mean = ts * invN;
            float var  = ts2 * invN - mean*mean;
            float sc   = gamma[t] * rsqrtf(var + EPSf);
            g_bnscale[t] = sc;
            g_bnshift[t] = beta[t] - mean*sc;
        }
    }
}

// ---------------- kernel 3: gate * BN(pt) + x ----------------
__global__ void out_kernel(const float4* __restrict__ x4, float4* __restrict__ out4)
{
    int i = blockIdx.x*256 + threadIdx.x;
    if (i >= Nn*Cc*(TVv/4)) return;
    int c = (i / (TVv/4)) & (Cc-1);
    int n = i / ((TVv/4)*Cc);
    float g  = g_gate[n*Cc + c];
    float sc = g_bnscale[c], sh = g_bnshift[c];
    float4 p  = ((const float4*)g_pt)[i];
    float4 xv = x4[i];
    float4 o;
    o.x = g*(p.x*sc + sh) + xv.x;
    o.y = g*(p.y*sc + sh) + xv.y;
    o.z = g*(p.z*sc + sh) + xv.z;
    o.w = g*(p.w*sc + sh) + xv.w;
    out4[i] = o;
}

// ---------------- launch ----------------
extern "C" void kernel_launch(void* const* d_in, const int* in_sizes, int n_in,
                              void* d_out, int out_size)
{
    const float* x     = (const float*)d_in[0];
    const float* Wv    = (const float*)d_in[1];
    const float* bv    = (const float*)d_in[2];
    const float* Wk    = (const float*)d_in[3];
    const float* bk    = (const float*)d_in[4];
    const float* Wq    = (const float*)d_in[5];
    const float* bq    = (const float*)d_in[6];
    const float* Wt    = (const float*)d_in[7];
    const float* bt    = (const float*)d_in[8];
    const float* gamma = (const float*)d_in[9];
    const float* beta  = (const float*)d_in[10];
    const float* W1    = (const float*)d_in[11];
    const float* b1    = (const float*)d_in[12];
    const float* W2    = (const float*)d_in[13];
    const float* b2    = (const float*)d_in[14];

    cudaFuncSetAttribute(attn_kernel, cudaFuncAttributeMaxDynamicSharedMemorySize, DSM_BYTES);

    proj_kernel<<<Nn*13, 128>>>(x, Wv, bv, Wk, bk, Wq, bq);
    attn_kernel<<<NCTA, 128, DSM_BYTES>>>(Wt, bt);
    gate_bn_kernel<<<Nn+1, 256>>>(W1, b1, W2, b2, gamma, beta);
    out_kernel<<<(Nn*Cc*(TVv/4) + 255)/256, 256>>>((const float4*)x, (float4*)d_out);
}

// round 17
// speedup vs baseline: 2.3705x; 1.0496x over previous
#include <cuda_runtime.h>
#include <cuda_bf16.h>

#define Nn 16
#define Cc 64
#define ICc 32
#define TVv 1600
#define QT 25              // query tiles of 64 per batch
#define NCTA (Nn*QT)       // 400
#define EPSf 1e-5f

typedef unsigned long long ull;
typedef unsigned int u32;

__device__ __forceinline__ ull pack2(float lo, float hi) {
    ull r; asm("mov.b64 %0, {%1, %2};" : "=l"(r) : "f"(lo), "f"(hi)); return r;
}
__device__ __forceinline__ void unpack2(ull v, float& lo, float& hi) {
    asm("mov.b64 {%0, %1}, %2;" : "=f"(lo), "=f"(hi) : "l"(v));
}
__device__ __forceinline__ ull ffma2(ull a, ull b, ull c) {
    ull d; asm("fma.rn.f32x2 %0, %1, %2, %3;" : "=l"(d) : "l"(a), "l"(b), "l"(c)); return d;
}
__device__ __forceinline__ u32 smem_u32(const void* p) {
    u32 a; asm("{ .reg .u64 t; cvta.to.shared.u64 t, %1; cvt.u32.u64 %0, t; }" : "=r"(a) : "l"(p));
    return a;
}

// m16n8k16 row.col bf16 -> f32, D accumulates in place
__device__ __forceinline__ void mma16816(float* c, const u32* a, u32 b0, u32 b1) {
    asm volatile(
        "mma.sync.aligned.m16n8k16.row.col.f32.bf16.bf16.f32 "
        "{%0,%1,%2,%3}, {%4,%5,%6,%7}, {%8,%9}, {%0,%1,%2,%3};"
        : "+f"(c[0]), "+f"(c[1]), "+f"(c[2]), "+f"(c[3])
        : "r"(a[0]), "r"(a[1]), "r"(a[2]), "r"(a[3]), "r"(b0), "r"(b1));
}

#define LDMX4(r, a) \
    asm volatile("ldmatrix.sync.aligned.m8n8.x4.shared.b16 {%0,%1,%2,%3}, [%4];" \
        : "=r"((r)[0]), "=r"((r)[1]), "=r"((r)[2]), "=r"((r)[3]) : "r"(a))

// pack two floats into bf16x2 hi + bf16x2 lo (hi/lo split)
__device__ __forceinline__ void split2(float a, float b, u32& hi, u32& lo) {
    __nv_bfloat16 ha = __float2bfloat16(a), hb = __float2bfloat16(b);
    __nv_bfloat162 H; H.x = ha; H.y = hb;
    __nv_bfloat162 L;
    L.x = __float2bfloat16(a - __bfloat162float(ha));
    L.y = __float2bfloat16(b - __bfloat162float(hb));
    hi = *(u32*)&H; lo = *(u32*)&L;
}

// ---------------- scratch ----------------
__device__ __nv_bfloat16 g_Qh[Nn*TVv*ICc];   // flash-queries (k_x), token-major
__device__ __nv_bfloat16 g_Ql[Nn*TVv*ICc];
__device__ __nv_bfloat16 g_Kh[Nn*TVv*ICc];   // flash-keys (q_x), token-major
__device__ __nv_bfloat16 g_Kl[Nn*TVv*ICc];
__device__ __nv_bfloat16 g_Vth[Nn*ICc*TVv];  // values channel-major [n][ic][tv]
__device__ __nv_bfloat16 g_Vtl[Nn*ICc*TVv];
__device__ float g_pt[Nn*Cc*TVv];
__device__ float g_avgpart[Nn*13*64];
__device__ float g_bnpart[NCTA*128];
__device__ float g_gate[Nn*Cc];
__device__ float g_bnscale[Cc];
__device__ float g_bnshift[Cc];

// ---------------- kernel 0: QKV projections (bf16 hi/lo) + x channel sums ----------------
__global__ __launch_bounds__(128)
void proj_kernel(const float* __restrict__ x,
                 const float* __restrict__ Wv, const float* __restrict__ bv,
                 const float* __restrict__ Wk, const float* __restrict__ bk,
                 const float* __restrict__ Wq, const float* __restrict__ bq)
{
    __shared__ float sW[3*ICc*Cc];
    __shared__ float s_part[4*64];
    int tid = threadIdx.x;
    for (int i = tid; i < ICc*Cc; i += 128) {
        sW[i]            = Wk[i];   // flash-Q from Wk (k_x rows of A)
        sW[ICc*Cc + i]   = Wq[i];   // flash-K from Wq (q_x cols of A)
        sW[2*ICc*Cc + i] = Wv[i];
    }
    int n = blockIdx.x / 13, chunk = blockIdx.x % 13;
    int tok = chunk*128 + tid;
    bool act = (tok < TVv);
    const float* xp = x + (long)n*Cc*TVv + tok;

    int lane = tid & 31, warp = tid >> 5;
    ull xp2[32];
    #pragma unroll
    for (int cp = 0; cp < 32; cp++) {
        float v0 = act ? xp[(long)(2*cp)  *TVv] : 0.f;
        float v1 = act ? xp[(long)(2*cp+1)*TVv] : 0.f;
        xp2[cp] = pack2(v0, v1);
        float s0 = v0, s1 = v1;
        #pragma unroll
        for (int o = 16; o > 0; o >>= 1) {
            s0 += __shfl_xor_sync(0xffffffffu, s0, o);
            s1 += __shfl_xor_sync(0xffffffffu, s1, o);
        }
        if (lane == 0) { s_part[warp*64 + 2*cp] = s0; s_part[warp*64 + 2*cp+1] = s1; }
    }
    __syncthreads();
    if (tid < 64) {
        g_avgpart[blockIdx.x*64 + tid] =
            s_part[tid] + s_part[64+tid] + s_part[128+tid] + s_part[192+tid];
    }
    if (!act) return;

    for (int m = 0; m < 3; m++) {
        const float* W  = sW + m*ICc*Cc;
        const float* bp = (m == 0) ? bk : ((m == 1) ? bq : bv);
        u32 rowHi[16], rowLo[16];
        #pragma unroll
        for (int og = 0; og < ICc; og += 4) {
            ull A[8];
            #pragma unroll
            for (int j = 0; j < 8; j++) A[j] = 0ULL;
            const ulonglong2* w0 = (const ulonglong2*)(W + (og  )*Cc);
            const ulonglong2* w1 = (const ulonglong2*)(W + (og+1)*Cc);
            const ulonglong2* w2 = (const ulonglong2*)(W + (og+2)*Cc);
            const ulonglong2* w3 = (const ulonglong2*)(W + (og+3)*Cc);
            #pragma unroll
            for (int i = 0; i < 16; i++) {
                ulonglong2 t0 = w0[i], t1 = w1[i], t2 = w2[i], t3 = w3[i];
                A[0] = ffma2(xp2[2*i], t0.x, A[0]); A[1] = ffma2(xp2[2*i+1], t0.y, A[1]);
                A[2] = ffma2(xp2[2*i], t1.x, A[2]); A[3] = ffma2(xp2[2*i+1], t1.y, A[3]);
                A[4] = ffma2(xp2[2*i], t2.x, A[4]); A[5] = ffma2(xp2[2*i+1], t2.y, A[5]);
                A[6] = ffma2(xp2[2*i], t3.x, A[6]); A[7] = ffma2(xp2[2*i+1], t3.y, A[7]);
            }
            float4 st;
            {
                float a0,a1,b0,b1;
                unpack2(A[0],a0,a1); unpack2(A[1],b0,b1); st.x = bp[og  ] + ((a0+b0)+(a1+b1));
                unpack2(A[2],a0,a1); unpack2(A[3],b0,b1); st.y = bp[og+1] + ((a0+b0)+(a1+b1));
                unpack2(A[4],a0,a1); unpack2(A[5],b0,b1); st.z = bp[og+2] + ((a0+b0)+(a1+b1));
                unpack2(A[6],a0,a1); unpack2(A[7],b0,b1); st.w = bp[og+3] + ((a0+b0)+(a1+b1));
            }
            if (m < 2) {
                split2(st.x, st.y, rowHi[og/2],   rowLo[og/2]);
                split2(st.z, st.w, rowHi[og/2+1], rowLo[og/2+1]);
            } else {
                long vb = (long)n*ICc*TVv + tok;
                float vv[4] = {st.x, st.y, st.z, st.w};
                #pragma unroll
                for (int j = 0; j < 4; j++) {
                    __nv_bfloat16 h = __float2bfloat16(vv[j]);
                    g_Vth[vb + (long)(og+j)*TVv] = h;
                    g_Vtl[vb + (long)(og+j)*TVv] = __float2bfloat16(vv[j] - __bfloat162float(h));
                }
            }
        }
        if (m == 0) {
            uint4* qh = (uint4*)(g_Qh + ((long)(n*TVv + tok))*ICc);
            uint4* ql = (uint4*)(g_Ql + ((long)(n*TVv + tok))*ICc);
            #pragma unroll
            for (int i = 0; i < 4; i++) {
                qh[i] = make_uint4(rowHi[4*i], rowHi[4*i+1], rowHi[4*i+2], rowHi[4*i+3]);
                ql[i] = make_uint4(rowLo[4*i], rowLo[4*i+1], rowLo[4*i+2], rowLo[4*i+3]);
            }
        } else if (m == 1) {
            uint4* kh = (uint4*)(g_Kh + ((long)(n*TVv + tok))*ICc);
            uint4* kl = (uint4*)(g_Kl + ((long)(n*TVv + tok))*ICc);
            #pragma unroll
            for (int i = 0; i < 4; i++) {
                kh[i] = make_uint4(rowHi[4*i], rowHi[4*i+1], rowHi[4*i+2], rowHi[4*i+3]);
                kl[i] = make_uint4(rowLo[4*i], rowLo[4*i+1], rowLo[4*i+2], rowLo[4*i+3]);
            }
        }
    }
}

// ---------------- kernel 1: HMMA flash attention + Trans conv + BN partials ----------------
#define KROW 80     // bytes per K smem row (40 bf16)
#define VROW 144    // bytes per V smem row (72 bf16)
#define OFF_KH0  0
#define OFF_KL0  5120
#define OFF_KH1  10240
#define OFF_KL1  15360
#define OFF_VH0  20480
#define OFF_VL0  25088
#define OFF_VH1  29696
#define OFF_VL1  34304
#define OFF_WT   38912
#define OFF_SA   47104        // 64 rows x 36 floats (144B rows)
#define DSM_BYTES (47104 + 9216)

__global__ __launch_bounds__(128)
void attn_kernel(const float* __restrict__ Wt, const float* __restrict__ bt)
{
    extern __shared__ char B[];
    __shared__ float s_bn[4*128];

    int tid = threadIdx.x, lane = tid & 31, warp = tid >> 5;
    int n = blockIdx.x / QT, qt = blockIdx.x % QT;
    int r  = lane >> 2;          // row within 16-row fragment
    int t2 = (lane & 3) * 2;     // col pair base

    u32 Bs = smem_u32(B);

    // ldmatrix per-lane base offsets (lane groups of 8 -> 4 8x8 matrices)
    int lrow8 = (lane & 7) + ((lane >> 4) << 3);       // row within 16-row tile
    u32 lhalf = ((lane >> 3) & 1) ? 16u : 0u;          // +16B for k+8 matrices
    u32 koff = (u32)lrow8 * KROW + lhalf;
    u32 voff = (u32)lrow8 * VROW + lhalf;

    for (int i = tid; i < 512; i += 128) s_bn[i] = 0.f;

    // stage Wt
    for (int i = tid; i < Cc*ICc; i += 128) ((float*)(B + OFF_WT))[i] = Wt[i];

    // ---- load Q fragments (per-warp 16 queries), hi and lo ----
    int qbase = qt*64 + warp*16;
    u32 aQh[8], aQl[8];
    {
        long i0 = ((long)(n*TVv + qbase + r))*ICc;
        #pragma unroll
        for (int kc = 0; kc < 2; kc++) {
            int f = kc*16 + t2;
            aQh[kc*4+0] = *(const u32*)(g_Qh + i0 + f);
            aQh[kc*4+1] = *(const u32*)(g_Qh + i0 + 8*ICc + f);
            aQh[kc*4+2] = *(const u32*)(g_Qh + i0 + f + 8);
            aQh[kc*4+3] = *(const u32*)(g_Qh + i0 + 8*ICc + f + 8);
            aQl[kc*4+0] = *(const u32*)(g_Ql + i0 + f);
            aQl[kc*4+1] = *(const u32*)(g_Ql + i0 + 8*ICc + f);
            aQl[kc*4+2] = *(const u32*)(g_Ql + i0 + f + 8);
            aQl[kc*4+3] = *(const u32*)(g_Ql + i0 + 8*ICc + f + 8);
        }
    }

    float O[16];
    #pragma unroll
    for (int i = 0; i < 16; i++) O[i] = 0.f;
    float l0 = 0.f, l1 = 0.f;

    auto stage = [&](int c, int buf) {
        const uint4* kh = (const uint4*)(g_Kh + ((long)(n*TVv + c*64))*ICc);
        const uint4* kl = (const uint4*)(g_Kl + ((long)(n*TVv + c*64))*ICc);
        char* KH = B + (buf ? OFF_KH1 : OFF_KH0);
        char* KL = B + (buf ? OFF_KL1 : OFF_KL0);
        #pragma unroll
        for (int t = 0; t < 2; t++) {
            int i = tid + t*128;          // 0..255
            int row = i >> 2, seg = i & 3;
            *(uint4*)(KH + row*KROW + seg*16) = kh[i];
            *(uint4*)(KL + row*KROW + seg*16) = kl[i];
        }
        char* VH = B + (buf ? OFF_VH1 : OFF_VH0);
        char* VL = B + (buf ? OFF_VL1 : OFF_VL0);
        #pragma unroll
        for (int t = 0; t < 2; t++) {
            int i = tid + t*128;
            int row = i >> 3, seg = i & 7;
            const uint4* vh = (const uint4*)(g_Vth + ((long)(n*ICc + row))*TVv + c*64);
            const uint4* vl = (const uint4*)(g_Vtl + ((long)(n*ICc + row))*TVv + c*64);
            *(uint4*)(VH + row*VROW + seg*16) = vh[seg];
            *(uint4*)(VL + row*VROW + seg*16) = vl[seg];
        }
    };

    stage(0, 0);
    __syncthreads();

    for (int c = 0; c < 25; c++) {
        int buf = c & 1;
        if (c < 24) stage(c+1, 1-buf);

        u32 KHb = Bs + (buf ? OFF_KH1 : OFF_KH0) + koff;
        u32 KLb = Bs + (buf ? OFF_KL1 : OFF_KL0) + koff;
        u32 VHb = Bs + (buf ? OFF_VH1 : OFF_VH0) + voff;
        u32 VLb = Bs + (buf ? OFF_VL1 : OFF_VL0) + voff;

        #pragma unroll
        for (int m = 0; m < 4; m++) {
            // ---- S tiles for keys m*16 .. m*16+15 ----
            float c4a[4] = {0.f, 0.f, 0.f, 0.f};
            float c4b[4] = {0.f, 0.f, 0.f, 0.f};
            u32 mko = (u32)(m*16*KROW);
            #pragma unroll
            for (int kc = 0; kc < 2; kc++) {
                u32 kh[4], kl[4];
                LDMX4(kh, KHb + mko + kc*32);
                LDMX4(kl, KLb + mko + kc*32);
                mma16816(c4a, aQh + kc*4, kh[0], kh[1]);
                mma16816(c4a, aQl + kc*4, kh[0], kh[1]);
                mma16816(c4a, aQh + kc*4, kl[0], kl[1]);
                mma16816(c4b, aQh + kc*4, kh[2], kh[3]);
                mma16816(c4b, aQl + kc*4, kh[2], kh[3]);
                mma16816(c4b, aQh + kc*4, kl[2], kl[3]);
            }
            float e[8];
            e[0] = __expf(c4a[0]); e[1] = __expf(c4a[1]);
            e[2] = __expf(c4a[2]); e[3] = __expf(c4a[3]);
            e[4] = __expf(c4b[0]); e[5] = __expf(c4b[1]);
            e[6] = __expf(c4b[2]); e[7] = __expf(c4b[3]);
            l0 += (e[0] + e[1]) + (e[4] + e[5]);
            l1 += (e[2] + e[3]) + (e[6] + e[7]);
            // ---- build P fragments (A-operand layout == C layout) ----
            u32 aPh[4], aPl[4];
            split2(e[0], e[1], aPh[0], aPl[0]);   // rows r,   keys sub0
            split2(e[2], e[3], aPh[1], aPl[1]);   // rows r+8, keys sub0
            split2(e[4], e[5], aPh[2], aPl[2]);   // rows r,   keys sub1
            split2(e[6], e[7], aPh[3], aPl[3]);   // rows r+8, keys sub1
            // ---- O += P * V for this 16-key slab ----
            u32 vh0[4], vh1[4], vl0[4], vl1[4];
            LDMX4(vh0, VHb + m*32);               // ic 0-15
            LDMX4(vh1, VHb + 16*VROW + m*32);     // ic 16-31
            LDMX4(vl0, VLb + m*32);
            LDMX4(vl1, VLb + 16*VROW + m*32);
            mma16816(O + 0,  aPh, vh0[0], vh0[1]);
            mma16816(O + 0,  aPl, vh0[0], vh0[1]);
            mma16816(O + 0,  aPh, vl0[0], vl0[1]);
            mma16816(O + 4,  aPh, vh0[2], vh0[3]);
            mma16816(O + 4,  aPl, vh0[2], vh0[3]);
            mma16816(O + 4,  aPh, vl0[2], vl0[3]);
            mma16816(O + 8,  aPh, vh1[0], vh1[1]);
            mma16816(O + 8,  aPl, vh1[0], vh1[1]);
            mma16816(O + 8,  aPh, vl1[0], vl1[1]);
            mma16816(O + 12, aPh, vh1[2], vh1[3]);
            mma16816(O + 12, aPl, vh1[2], vh1[3]);
            mma16816(O + 12, aPh, vl1[2], vl1[3]);
        }
        __syncthreads();
    }

    // ---- reduce l across the 4 lanes of each row group ----
    #pragma unroll
    for (int o = 1; o <= 2; o <<= 1) {
        l0 += __shfl_xor_sync(0xffffffffu, l0, o);
        l1 += __shfl_xor_sync(0xffffffffu, l1, o);
    }
    float inv0 = 1.f / l0, inv1 = 1.f / l1;

    // ---- write normalized p to sA [64 q][36 floats] ----
    float* SA = (float*)(B + OFF_SA);
    #pragma unroll
    for (int jo = 0; jo < 4; jo++) {
        int q0 = warp*16 + r;
        float2 v0; v0.x = O[jo*4+0]*inv0; v0.y = O[jo*4+1]*inv0;
        float2 v1; v1.x = O[jo*4+2]*inv1; v1.y = O[jo*4+3]*inv1;
        *(float2*)(SA + q0*36 + jo*8 + t2)       = v0;
        *(float2*)(SA + (q0+8)*36 + jo*8 + t2)   = v1;
    }
    __syncthreads();

    // ---- fused Trans_s 1x1 conv + BN partial sums (64 q x 64 ch) ----
    long ptbase = (long)n*Cc*TVv + (long)qt*64;
    const ulonglong2* Wts = (const ulonglong2*)(B + OFF_WT);
    for (int k = 0; k < 32; k++) {
        int idx = tid + k*128;
        int c2 = idx >> 6;
        int qq = idx & 63;
        const ulonglong2* wr = Wts + c2*8;
        const ulonglong2* pr = (const ulonglong2*)(SA + qq*36);
        ull va = 0ULL, vb = 0ULL;
        #pragma unroll
        for (int i = 0; i < 8; i++) {
            ulonglong2 w = wr[i], p = pr[i];
            va = ffma2(w.x, p.x, va);
            vb = ffma2(w.y, p.y, vb);
        }
        float a0, a1, b0, b1;
        unpack2(va, a0, a1); unpack2(vb, b0, b1);
        float val = bt[c2] + ((a0 + b0) + (a1 + b1));
        g_pt[ptbase + (long)c2*TVv + qq] = val;

        float s = val, s2 = val*val;
        #pragma unroll
        for (int o = 16; o > 0; o >>= 1) {
            s  += __shfl_xor_sync(0xffffffffu, s,  o);
            s2 += __shfl_xor_sync(0xffffffffu, s2, o);
        }
        if (lane == 0) {
            s_bn[warp*128 + c2]      += s;
            s_bn[warp*128 + 64 + c2] += s2;
        }
    }
    __syncthreads();
    if (tid < 128) {
        g_bnpart[blockIdx.x*128 + tid] =
            s_bn[tid] + s_bn[128+tid] + s_bn[256+tid] + s_bn[384+tid];
    }
}

// ---------------- kernel 2: channel gate MLP + BN finalize ----------------
__global__ __launch_bounds__(256)
void gate_bn_kernel(const float* __restrict__ W1, const float* __restrict__ b1,
                    const float* __restrict__ W2, const float* __restrict__ b2,
                    const float* __restrict__ gamma, const float* __restrict__ beta)
{
    int t = threadIdx.x;
    if (blockIdx.x < Nn) {
        int n = blockIdx.x;
        __shared__ float s_avg[64], s_h[4];
        if (t < 64) {
            float s = 0.f;
            for (int chnk = 0; chnk < 13; chnk++) s += g_avgpart[(n*13 + chnk)*64 + t];
            s_avg[t] = s * (1.f / (float)TVv);
        }
        __syncthreads();
        if (t < 4) {
            float hsum = b1[t];
            for (int c = 0; c < 64; c++) hsum += W1[t*64 + c] * s_avg[c];
            s_h[t] = fmaxf(hsum, 0.f);
        }
        __syncthreads();
        if (t < 64) {
            float g = b2[t];
            #pragma unroll
            for (int j = 0; j < 4; j++) g += W2[t*4 + j] * s_h[j];
            g_gate[n*64 + t] = 1.f / (1.f + __expf(-g));
        }
    } else {
        __shared__ float rs[4][64], rs2[4][64];
        int ch = t & 63, pp = t >> 6;
        float s = 0.f, s2 = 0.f;
        for (int b = pp*100; b < pp*100 + 100; b++) {
            s  += g_bnpart[b*128 + ch];
            s2 += g_bnpart[b*128 + 64 + ch];
        }
        rs[pp][ch] = s; rs2[pp][ch] = s2;
        __syncthreads();
        if (t < 64) {
            float ts  = (rs[0][t]  + rs[1][t])  + (rs[2][t]  + rs[3][t]);
            float ts2 = (rs2[0][t] + rs2[1][t]) + (rs2[2][t] + rs2[3][t]);
            const float invN = 1.f / (float)(Nn * TVv);
            float mean = ts * invN;
            float var  = ts2 * invN - mean*mean;
            float sc   = gamma[t] * rsqrtf(var + EPSf);
            g_bnscale[t] = sc;
            g_bnshift[t] = beta[t] - mean*sc;
        }
    }
}

// ---------------- kernel 3: gate * BN(pt) + x ----------------
__global__ void out_kernel(const float4* __restrict__ x4, float4* __restrict__ out4)
{
    int i = blockIdx.x*256 + threadIdx.x;
    if (i >= Nn*Cc*(TVv/4)) return;
    int c = (i / (TVv/4)) & (Cc-1);
    int n = i / ((TVv/4)*Cc);
    float g  = g_gate[n*Cc + c];
    float sc = g_bnscale[c], sh = g_bnshift[c];
    float4 p  = ((const float4*)g_pt)[i];
    float4 xv = x4[i];
    float4 o;
    o.x = g*(p.x*sc + sh) + xv.x;
    o.y = g*(p.y*sc + sh) + xv.y;
    o.z = g*(p.z*sc + sh) + xv.z;
    o.w = g*(p.w*sc + sh) + xv.w;
    out4[i] = o;
}

// ---------------- launch ----------------
extern "C" void kernel_launch(void* const* d_in, const int* in_sizes, int n_in,
                              void* d_out, int out_size)
{
    const float* x     = (const float*)d_in[0];
    const float* Wv    = (const float*)d_in[1];
    const float* bv    = (const float*)d_in[2];
    const float* Wk    = (const float*)d_in[3];
    const float* bk    = (const float*)d_in[4];
    const float* Wq    = (const float*)d_in[5];
    const float* bq    = (const float*)d_in[6];
    const float* Wt    = (const float*)d_in[7];
    const float* bt    = (const float*)d_in[8];
    const float* gamma = (const float*)d_in[9];
    const float* beta  = (const float*)d_in[10];
    const float* W1    = (const float*)d_in[11];
    const float* b1    = (const float*)d_in[12];
    const float* W2    = (const float*)d_in[13];
    const float* b2    = (const float*)d_in[14];

    cudaFuncSetAttribute(attn_kernel, cudaFuncAttributeMaxDynamicSharedMemorySize, DSM_BYTES);

    proj_kernel<<<Nn*13, 128>>>(x, Wv, bv, Wk, bk, Wq, bq);
    attn_kernel<<<NCTA, 128, DSM_BYTES>>>(Wt, bt);
    gate_bn_kernel<<<Nn+1, 256>>>(W1, b1, W2, b2, gamma, beta);
    out_kernel<<<(Nn*Cc*(TVv/4) + 255)/256, 256>>>((const float4*)x, (float4*)d_out);
}